// round 3
// baseline (speedup 1.0000x reference)
#include <cuda_runtime.h>
#include <cuda_bf16.h>
#include <cstdint>

#define EPSV 1e-5f
#define N_MAX   163904      // >= N+1 rows (N = 160000)
#define NP_MAX  65792       // >= NPOOL+1 rows

// -------- persistent scratch (no allocs allowed) --------
__device__ float g_x1[(size_t)N_MAX * 64];
__device__ float g_x2[(size_t)N_MAX * 64];
__device__ float g_xp[(size_t)NP_MAX * 64];
__device__ float g_y3[(size_t)NP_MAX * 128];
__device__ __nv_bfloat16 g_xh[(size_t)N_MAX * 64];
__device__ __nv_bfloat16 g_xl[(size_t)N_MAX * 64];
__device__ int   g_nbr [(size_t)N_MAX * 27];
__device__ int   g_nbr2[(size_t)NP_MAX * 27];
__device__ float g_stats[768];
__device__ __nv_bfloat16 g_w2h[27 * 64 * 64],  g_w2l[27 * 64 * 64];
__device__ __nv_bfloat16 g_w3h[27 * 128 * 64], g_w3l[27 * 128 * 64];

// -------- PTX helpers (plain sm_103-safe: cp.async / ldmatrix / mma.sync) ----
__device__ __forceinline__ uint32_t smem_u32(const void* p) {
    uint32_t a;
    asm("{ .reg .u64 t; cvta.to.shared.u64 t, %1; cvt.u32.u64 %0, t; }" : "=r"(a) : "l"(p));
    return a;
}
#define SWZ(o) ((uint32_t)(o) ^ ((((uint32_t)(o)) >> 3) & 0x70))

__device__ __forceinline__ void cpa16(uint32_t d, const void* s) {
    asm volatile("cp.async.cg.shared.global [%0], [%1], 16;" :: "r"(d), "l"(s));
}
__device__ __forceinline__ void cpa_commit() {
    asm volatile("cp.async.commit_group;" ::: "memory");
}
template<int NN>
__device__ __forceinline__ void cpa_wait() {
    asm volatile("cp.async.wait_group %0;" :: "n"(NN) : "memory");
}
__device__ __forceinline__ void ldsm4(uint32_t* r, uint32_t addr) {
    asm volatile("ldmatrix.sync.aligned.m8n8.x4.shared.b16 {%0,%1,%2,%3}, [%4];"
                 : "=r"(r[0]), "=r"(r[1]), "=r"(r[2]), "=r"(r[3]) : "r"(addr));
}
__device__ __forceinline__ void mma16816(float* c, const uint32_t* a, const uint32_t* b) {
    asm volatile("mma.sync.aligned.m16n8k16.row.col.f32.bf16.bf16.f32 "
                 "{%0,%1,%2,%3}, {%4,%5,%6,%7}, {%8,%9}, {%0,%1,%2,%3};"
                 : "+f"(c[0]), "+f"(c[1]), "+f"(c[2]), "+f"(c[3])
                 : "r"(a[0]), "r"(a[1]), "r"(a[2]), "r"(a[3]), "r"(b[0]), "r"(b[1]));
}

// -------- utilities --------
__global__ void fill_int_kernel(int* __restrict__ p, int n, int v) {
    int i = blockIdx.x * blockDim.x + threadIdx.x;
    if (i < n) p[i] = v;
}
__global__ void build_nbr_kernel(const int* __restrict__ km_in, const int* __restrict__ km_out,
                                 int* __restrict__ nbr, int M, int Nr) {
    int idx = blockIdx.x * blockDim.x + threadIdx.x;
    if (idx >= 27 * M) return;
    int i = km_in[idx];
    if (i < Nr) {
        int k = idx / M;
        nbr[k * Nr + km_out[idx]] = i;
    }
}
__global__ void wprep_kernel(const float* __restrict__ W, __nv_bfloat16* __restrict__ Wh,
                             __nv_bfloat16* __restrict__ Wl, int CO, int total) {
    int idx = blockIdx.x * blockDim.x + threadIdx.x;
    if (idx >= total) return;
    int k = idx / (64 * CO), rem = idx % (64 * CO);
    int c = rem / CO, n = rem % CO;
    float w = W[idx];
    __nv_bfloat16 h = __float2bfloat16(w);
    __nv_bfloat16 l = __float2bfloat16(w - __bfloat162float(h));
    size_t o = ((size_t)k * CO + n) * 64 + c;   // [k][out][in]
    Wh[o] = h; Wl[o] = l;
}

// -------- conv1: C_in=1 -> 64 (FFMA, cheap) --------
__global__ void __launch_bounds__(256) conv1_kernel(const float* __restrict__ feats,
                                                    const float* __restrict__ W1,
                                                    float* __restrict__ out,
                                                    const int* __restrict__ nbr, int Nr) {
    __shared__ float fs[27 * 64];
    __shared__ float ws[27 * 64];
    int t = threadIdx.x;
    int r0 = blockIdx.x * 64;
    for (int i = t; i < 27 * 64; i += 256) ws[i] = W1[i];
    for (int i = t; i < 27 * 64; i += 256) {
        int k = i >> 6, rr = i & 63, r = r0 + rr;
        float v = 0.f;
        if (r < Nr) {
            int g = nbr[k * Nr + r];
            if (g < Nr) v = feats[g];
        }
        fs[i] = v;
    }
    __syncthreads();
    int c = t & 63, rg = t >> 6;
    #pragma unroll
    for (int ri = 0; ri < 16; ri++) {
        int rr = rg * 16 + ri, r = r0 + rr;
        if (r < Nr) {
            float acc = 0.f;
            #pragma unroll
            for (int k = 0; k < 27; k++) acc += fs[k * 64 + rr] * ws[k * 64 + c];
            out[(size_t)r * 64 + c] = acc;
        }
    }
}

// -------- HMMA gather conv: 128 rows x CO per block, bf16 3-pass split --------
// smem stage layout: Ah[16K] Al[16K] Bh[CO*128] Bl[CO*128]
template<int CO>
__global__ void __launch_bounds__(256) conv_mma_kernel(const __nv_bfloat16* __restrict__ xh,
                                                       const __nv_bfloat16* __restrict__ xl,
                                                       const __nv_bfloat16* __restrict__ Wh,
                                                       const __nv_bfloat16* __restrict__ Wl,
                                                       float* __restrict__ out,
                                                       const int* __restrict__ nbr, int Nr) {
    constexpr int NT = CO / 8;                 // n-tiles per warp
    constexpr uint32_t B_BYTES = CO * 128;
    constexpr uint32_t STAGE = 32768 + 2 * B_BYTES;
    extern __shared__ char smem_raw[];
    const uint32_t sb = (smem_u32(smem_raw) + 1023) & ~1023u;

    const int t = threadIdx.x, w = t >> 5, l = t & 31;
    const int r0 = blockIdx.x * 128;

    // producer mapping
    const int arow = t >> 1, ahalf = t & 1;        // A: 2 threads/row, 64B half each
    const int brow = (t >> 1) & (CO - 1), bhalf = t & 1;
    const bool bact = (CO == 128) || (t < 128);

    float acc[NT][4];
    #pragma unroll
    for (int nt = 0; nt < NT; nt++)
        #pragma unroll
        for (int i = 0; i < 4; i++) acc[nt][i] = 0.f;

    // consumer lane addressing (constant across k)
    const uint32_t aoff = SWZ((w * 16 + ((l >> 3) & 1) * 8 + (l & 7)) * 128 + ((l >> 4) & 1) * 16);

    auto load_stage = [&](int k, uint32_t base) {
        int gr = r0 + arow;
        int g = (gr < Nr) ? __ldg(nbr + (size_t)k * Nr + gr) : Nr;   // row Nr = zero row
        const char* sH = (const char*)(xh + (size_t)g * 64) + ahalf * 64;
        const char* sL = (const char*)(xl + (size_t)g * 64) + ahalf * 64;
        #pragma unroll
        for (int j = 0; j < 4; j++) {
            uint32_t off = SWZ(arow * 128 + ahalf * 64 + j * 16);
            cpa16(base + off, sH + j * 16);
            cpa16(base + 16384 + off, sL + j * 16);
        }
        if (bact) {
            const char* wH = (const char*)(Wh + ((size_t)k * CO + brow) * 64) + bhalf * 64;
            const char* wL = (const char*)(Wl + ((size_t)k * CO + brow) * 64) + bhalf * 64;
            #pragma unroll
            for (int j = 0; j < 4; j++) {
                uint32_t off = SWZ(brow * 128 + bhalf * 64 + j * 16);
                cpa16(base + 32768 + off, wH + j * 16);
                cpa16(base + 32768 + B_BYTES + off, wL + j * 16);
            }
        }
    };

    load_stage(0, sb);
    cpa_commit();

    for (int k = 0; k < 27; k++) {
        const uint32_t base = sb + (uint32_t)(k & 1) * STAGE;
        if (k < 26) {
            load_stage(k + 1, sb + (uint32_t)((k + 1) & 1) * STAGE);
            cpa_commit();
            cpa_wait<1>();
        } else {
            cpa_wait<0>();
        }
        __syncthreads();

        const uint32_t bbase = base + 32768;
        #pragma unroll
        for (int kc = 0; kc < 4; kc++) {
            uint32_t ah[4], al[4];
            uint32_t aaddr = base + (aoff ^ SWZ(0) ^ 0);   // aoff already swizzled w/o kc
            // recompute with kc offset (swizzle is XOR-linear in the 16B index bits)
            uint32_t rowbits = (w * 16 + ((l >> 3) & 1) * 8 + (l & 7)) * 128 + ((l >> 4) & 1) * 16 + kc * 32;
            aaddr = base + SWZ(rowbits);
            ldsm4(ah, aaddr);
            ldsm4(al, aaddr + 16384);

            uint32_t bb[NT][2];
            const uint32_t nrowbits = (((l >> 4) & 1) * 8 + (l & 7)) * 128 + ((l >> 3) & 1) * 16 + kc * 32;
            #pragma unroll
            for (int np = 0; np < NT / 2; np++) {
                uint32_t baddr = bbase + SWZ(np * 16 * 128 + nrowbits);
                ldsm4(&bb[2 * np][0], baddr);
            }
            #pragma unroll
            for (int nt = 0; nt < NT; nt++) mma16816(acc[nt], ah, bb[nt]);   // hh
            #pragma unroll
            for (int nt = 0; nt < NT; nt++) mma16816(acc[nt], al, bb[nt]);   // lh
            #pragma unroll
            for (int np = 0; np < NT / 2; np++) {
                uint32_t baddr = bbase + B_BYTES + SWZ(np * 16 * 128 + nrowbits);
                ldsm4(&bb[2 * np][0], baddr);
            }
            #pragma unroll
            for (int nt = 0; nt < NT; nt++) mma16816(acc[nt], ah, bb[nt]);   // hl
        }
        __syncthreads();
    }

    // epilogue: warp w owns rows [16w, 16w+16)
    const int row0 = r0 + w * 16 + (l >> 2);
    const int row1 = row0 + 8;
    #pragma unroll
    for (int nt = 0; nt < NT; nt++) {
        int col = nt * 8 + 2 * (l & 3);
        if (row0 < Nr) *(float2*)(out + (size_t)row0 * CO + col) = make_float2(acc[nt][0], acc[nt][1]);
        if (row1 < Nr) *(float2*)(out + (size_t)row1 * CO + col) = make_float2(acc[nt][2], acc[nt][3]);
    }
}

// -------- BN stats --------
template<int C>
__global__ void __launch_bounds__(256) bn_reduce_kernel(const float* __restrict__ x, int rows,
                                                        float* __restrict__ sumo, float* __restrict__ sqo) {
    constexpr int G = 256 / C;
    int t = threadIdx.x, c = t & (C - 1), rg = t / C;
    float s = 0.f, q = 0.f;
    for (int r = blockIdx.x * G + rg; r < rows; r += gridDim.x * G) {
        float v = x[(size_t)r * C + c];
        s += v; q = fmaf(v, v, q);
    }
    __shared__ float sh[512];
    sh[t] = s; sh[256 + t] = q;
    __syncthreads();
    if (rg == 0) {
        #pragma unroll
        for (int g = 1; g < G; g++) { s += sh[g * C + c]; q += sh[256 + g * C + c]; }
        atomicAdd(&sumo[c], s);
        atomicAdd(&sqo[c], q);
    }
}

// BN+ReLU -> bf16 hi/lo pair
__global__ void __launch_bounds__(256) bn_apply_pair_kernel(const float* __restrict__ x,
                                                            __nv_bfloat16* __restrict__ yh,
                                                            __nv_bfloat16* __restrict__ yl, int rows,
                                                            const float* __restrict__ gam, const float* __restrict__ bet,
                                                            const float* __restrict__ sums, const float* __restrict__ sqs) {
    size_t total = (size_t)rows * 64;
    float invn = 1.f / (float)rows;
    for (size_t idx = (size_t)blockIdx.x * 256 + threadIdx.x; idx < total; idx += (size_t)gridDim.x * 256) {
        int c = (int)(idx & 63);
        float mu = sums[c] * invn;
        float var = fmaf(-mu, mu, sqs[c] * invn);
        float scl = gam[c] * rsqrtf(var + EPSV);
        float v = fmaxf(fmaf(x[idx] - mu, scl, bet[c]), 0.f);
        __nv_bfloat16 h = __float2bfloat16(v);
        yh[idx] = h;
        yl[idx] = __float2bfloat16(v - __bfloat162float(h));
    }
}

// BN+ReLU fused with segment maxpool (atomicMax on non-negative floats)
__global__ void __launch_bounds__(256) bn_apply_pool_kernel(const float* __restrict__ x,
                                                            const int* __restrict__ seg,
                                                            float* __restrict__ xp, int rows,
                                                            const float* __restrict__ gam, const float* __restrict__ bet,
                                                            const float* __restrict__ sums, const float* __restrict__ sqs) {
    size_t total = (size_t)rows * 64;
    float invn = 1.f / (float)rows;
    for (size_t idx = (size_t)blockIdx.x * 256 + threadIdx.x; idx < total; idx += (size_t)gridDim.x * 256) {
        int c = (int)(idx & 63);
        int r = (int)(idx >> 6);
        float mu = sums[c] * invn;
        float var = fmaf(-mu, mu, sqs[c] * invn);
        float scl = gam[c] * rsqrtf(var + EPSV);
        float v = fmaxf(fmaf(x[idx] - mu, scl, bet[c]), 0.f);
        atomicMax((unsigned int*)&xp[(size_t)seg[r] * 64 + c], __float_as_uint(v));
    }
}

__global__ void __launch_bounds__(256) convert_pair_kernel(const float* __restrict__ x,
                                                           __nv_bfloat16* __restrict__ yh,
                                                           __nv_bfloat16* __restrict__ yl, int rows) {
    size_t total = (size_t)rows * 64;
    for (size_t idx = (size_t)blockIdx.x * 256 + threadIdx.x; idx < total; idx += (size_t)gridDim.x * 256) {
        float v = x[idx];
        __nv_bfloat16 h = __float2bfloat16(v);
        yh[idx] = h;
        yl[idx] = __float2bfloat16(v - __bfloat162float(h));
    }
}

template<int C>
__global__ void __launch_bounds__(256) bn_apply_kernel(const float* __restrict__ x, float* __restrict__ y,
                                                       int rows,
                                                       const float* __restrict__ gam, const float* __restrict__ bet,
                                                       const float* __restrict__ sums, const float* __restrict__ sqs) {
    size_t total = (size_t)rows * C;
    float invn = 1.f / (float)rows;
    for (size_t idx = (size_t)blockIdx.x * 256 + threadIdx.x; idx < total; idx += (size_t)gridDim.x * 256) {
        int c = (int)(idx & (C - 1));
        float mu = sums[c] * invn;
        float var = fmaf(-mu, mu, sqs[c] * invn);
        float scl = gam[c] * rsqrtf(var + EPSV);
        float v = fmaf(x[idx] - mu, scl, bet[c]);
        y[idx] = fmaxf(v, 0.f);
    }
}

// -------- launch --------
extern "C" void kernel_launch(void* const* d_in, const int* in_sizes, int n_in,
                              void* d_out, int out_size) {
    const float* feats = (const float*)d_in[0];
    const float* W1    = (const float*)d_in[1];
    const float* g1    = (const float*)d_in[3];
    const float* be1   = (const float*)d_in[4];
    const float* W2    = (const float*)d_in[5];
    const float* g2    = (const float*)d_in[7];
    const float* be2   = (const float*)d_in[8];
    const float* W3    = (const float*)d_in[9];
    const float* g3    = (const float*)d_in[11];
    const float* be3   = (const float*)d_in[12];
    const int* km_in   = (const int*)d_in[13];
    const int* km_out  = (const int*)d_in[14];
    const int* seg     = (const int*)d_in[15];
    const int* km2_in  = (const int*)d_in[16];
    const int* km2_out = (const int*)d_in[17];

    int N  = in_sizes[0];
    int M  = in_sizes[13] / 27;
    int M2 = in_sizes[16] / 27;
    int NP = out_size / 128;

    float *x1, *x2, *xp, *y3, *stats; int *nbr, *nbr2;
    __nv_bfloat16 *xh, *xl, *w2h, *w2l, *w3h, *w3l;
    cudaGetSymbolAddress((void**)&x1, g_x1);
    cudaGetSymbolAddress((void**)&x2, g_x2);
    cudaGetSymbolAddress((void**)&xp, g_xp);
    cudaGetSymbolAddress((void**)&y3, g_y3);
    cudaGetSymbolAddress((void**)&nbr, g_nbr);
    cudaGetSymbolAddress((void**)&nbr2, g_nbr2);
    cudaGetSymbolAddress((void**)&stats, g_stats);
    cudaGetSymbolAddress((void**)&xh, g_xh);
    cudaGetSymbolAddress((void**)&xl, g_xl);
    cudaGetSymbolAddress((void**)&w2h, g_w2h);
    cudaGetSymbolAddress((void**)&w2l, g_w2l);
    cudaGetSymbolAddress((void**)&w3h, g_w3h);
    cudaGetSymbolAddress((void**)&w3l, g_w3l);

    constexpr int SMEM2 = 2 * (32768 + 2 * 64 * 128)  + 1024;   // 99328
    constexpr int SMEM3 = 2 * (32768 + 2 * 128 * 128) + 1024;   // 132096
    cudaFuncSetAttribute(conv_mma_kernel<64>,  cudaFuncAttributeMaxDynamicSharedMemorySize, SMEM2);
    cudaFuncSetAttribute(conv_mma_kernel<128>, cudaFuncAttributeMaxDynamicSharedMemorySize, SMEM3);

    cudaMemsetAsync(stats, 0, 768 * sizeof(float), 0);
    cudaMemsetAsync(xh + (size_t)N * 64, 0, 64 * sizeof(__nv_bfloat16), 0);
    cudaMemsetAsync(xl + (size_t)N * 64, 0, 64 * sizeof(__nv_bfloat16), 0);
    cudaMemsetAsync(xp, 0, (size_t)NP * 64 * sizeof(float), 0);

    // neighbor tables + split/transposed weights
    fill_int_kernel<<<(27 * N + 255) / 256, 256>>>(nbr, 27 * N, N);
    build_nbr_kernel<<<(27 * M + 255) / 256, 256>>>(km_in, km_out, nbr, M, N);
    fill_int_kernel<<<(27 * NP + 255) / 256, 256>>>(nbr2, 27 * NP, NP);
    build_nbr_kernel<<<(27 * M2 + 255) / 256, 256>>>(km2_in, km2_out, nbr2, M2, NP);
    wprep_kernel<<<(27 * 64 * 64 + 255) / 256, 256>>>(W2, w2h, w2l, 64, 27 * 64 * 64);
    wprep_kernel<<<(27 * 64 * 128 + 255) / 256, 256>>>(W3, w3h, w3l, 128, 27 * 64 * 128);

    // layer 1
    conv1_kernel<<<(N + 63) / 64, 256>>>(feats, W1, x1, nbr, N);
    bn_reduce_kernel<64><<<592, 256>>>(x1, N, stats + 0, stats + 128);
    bn_apply_pair_kernel<<<1184, 256>>>(x1, xh, xl, N, g1, be1, stats + 0, stats + 128);

    // layer 2 (HMMA)
    conv_mma_kernel<64><<<(N + 127) / 128, 256, SMEM2>>>(xh, xl, w2h, w2l, x2, nbr, N);
    bn_reduce_kernel<64><<<592, 256>>>(x2, N, stats + 256, stats + 384);
    bn_apply_pool_kernel<<<1184, 256>>>(x2, seg, xp, N, g2, be2, stats + 256, stats + 384);

    // pooled -> bf16 pair (reuse xh/xl), zero row at NP
    convert_pair_kernel<<<1184, 256>>>(xp, xh, xl, NP);
    cudaMemsetAsync(xh + (size_t)NP * 64, 0, 64 * sizeof(__nv_bfloat16), 0);
    cudaMemsetAsync(xl + (size_t)NP * 64, 0, 64 * sizeof(__nv_bfloat16), 0);

    // layer 3 (HMMA)
    conv_mma_kernel<128><<<(NP + 127) / 128, 256, SMEM3>>>(xh, xl, w3h, w3l, y3, nbr2, NP);
    bn_reduce_kernel<128><<<592, 256>>>(y3, NP, stats + 512, stats + 640);
    bn_apply_kernel<128><<<1184, 256>>>(y3, (float*)d_out, NP, g3, be3, stats + 512, stats + 640);
}

// round 4
// speedup vs baseline: 1.6099x; 1.6099x over previous
#include <cuda_runtime.h>
#include <cstdint>

#define EPSV 1e-5f
#define N_MAX   163904      // >= N+1 rows (N = 160000)
#define NP_MAX  65792       // >= NPOOL+1 rows

// -------- persistent scratch (no allocs allowed) --------
__device__ float g_x1[(size_t)N_MAX * 64];
__device__ float g_x2[(size_t)N_MAX * 64];
__device__ float g_xp[(size_t)NP_MAX * 64];
__device__ float g_y3[(size_t)NP_MAX * 128];
__device__ int   g_nbr [(size_t)N_MAX * 27];
__device__ int   g_nbr2[(size_t)NP_MAX * 27];
__device__ float g_stats[768];

typedef unsigned long long u64t;

__device__ __forceinline__ u64t pack2(float a, float b) {
    u64t r; unsigned x = __float_as_uint(a), y = __float_as_uint(b);
    asm("mov.b64 %0, {%1, %2};" : "=l"(r) : "r"(x), "r"(y));
    return r;
}
__device__ __forceinline__ void fma2(u64t& d, u64t a, u64t b) {
    asm("fma.rn.f32x2 %0, %1, %2, %0;" : "+l"(d) : "l"(a), "l"(b));
}
__device__ __forceinline__ float2 unpack2(u64t v) {
    unsigned lo, hi; asm("mov.b64 {%0, %1}, %2;" : "=r"(lo), "=r"(hi) : "l"(v));
    return make_float2(__uint_as_float(lo), __uint_as_float(hi));
}

// ---------------------------------------------------------------- init
__global__ void zstats_kernel(float* __restrict__ stats) {
    if (threadIdx.x < 768) stats[threadIdx.x] = 0.f;
}
__global__ void initbig_kernel(int* __restrict__ nbr, int* __restrict__ nbr2,
                               float* __restrict__ xp, float* __restrict__ x1,
                               int N, int NP) {
    int i = blockIdx.x * blockDim.x + threadIdx.x;
    if (i < 27 * N) nbr[i] = N;
    if (i < 27 * NP) nbr2[i] = NP;
    if (i < (NP + 1) * 64) xp[i] = 0.f;
    if (i < 64) x1[(size_t)N * 64 + i] = 0.f;
}
__global__ void build_nbr_kernel(const int* __restrict__ km_in, const int* __restrict__ km_out,
                                 int* __restrict__ nbr, int M, int Nr) {
    int idx = blockIdx.x * blockDim.x + threadIdx.x;
    if (idx >= 27 * M) return;
    int i = km_in[idx];
    if (i < Nr) {
        int k = idx / M;
        nbr[k * Nr + km_out[idx]] = i;
    }
}

// ---------------------------------------------------------------- conv1: 1 -> 64 channels, fused stats
__global__ void __launch_bounds__(256) conv1_kernel(const float* __restrict__ feats,
                                                    const float* __restrict__ W1,
                                                    float* __restrict__ out,
                                                    const int* __restrict__ nbr, int Nr,
                                                    float* __restrict__ stats) {
    __shared__ float fs[27 * 64];
    __shared__ float ws[27 * 64];
    __shared__ float sh[512];
    int t = threadIdx.x;
    int r0 = blockIdx.x * 64;
    for (int i = t; i < 27 * 64; i += 256) ws[i] = W1[i];
    for (int i = t; i < 27 * 64; i += 256) {
        int k = i >> 6, rr = i & 63, r = r0 + rr;
        float v = 0.f;
        if (r < Nr) {
            int g = nbr[k * Nr + r];
            if (g < Nr) v = feats[g];
        }
        fs[i] = v;
    }
    __syncthreads();
    int c = t & 63, rg = t >> 6;
    float s = 0.f, q = 0.f;
    #pragma unroll
    for (int ri = 0; ri < 16; ri++) {
        int rr = rg * 16 + ri, r = r0 + rr;
        if (r < Nr) {
            float acc = 0.f;
            #pragma unroll
            for (int k = 0; k < 27; k++) acc += fs[k * 64 + rr] * ws[k * 64 + c];
            out[(size_t)r * 64 + c] = acc;
            s += acc; q = fmaf(acc, acc, q);
        }
    }
    sh[t] = s; sh[256 + t] = q;
    __syncthreads();
    if (rg == 0) {
        #pragma unroll
        for (int g = 1; g < 4; g++) { s += sh[g * 64 + c]; q += sh[256 + g * 64 + c]; }
        atomicAdd(&stats[c], s);
        atomicAdd(&stats[128 + c], q);
    }
}

// ---------------------------------------------------------------- fused gather-conv (FFMA2, 8x8 thread tiles)
// block tile: MROWS x CO ; K = 27 offsets x 64 channels; optional inline BN+ReLU on gather
template<int CO, int MROWS, bool APPLY_BN>
__global__ void __launch_bounds__(256) conv_ffma_kernel(
    const float* __restrict__ x, const float* __restrict__ W,
    float* __restrict__ out, const int* __restrict__ nbr, int Nr,
    const float* __restrict__ sums, const float* __restrict__ sqs,
    const float* __restrict__ gam, const float* __restrict__ bet, float invn,
    float* __restrict__ oS, float* __restrict__ oQ)
{
    constexpr int TPR   = 256 / MROWS;        // threads per gathered row (1 or 2)
    constexpr int CHUNK = 16 / TPR;           // float4 chunks per thread per row
    constexpr int HALF  = CHUNK / 2;
    constexpr int TC    = CO / 8;             // threads along cols
    constexpr int WCNT  = 64 * CO / (4 * 256);// float4 of weights per thread
    extern __shared__ float sm[];
    float* XT0 = sm;
    float* XT1 = sm + 64 * MROWS;
    float* WS0 = sm + 2 * 64 * MROWS;
    float* WS1 = WS0 + 64 * CO;
    float* bnc = WS0 + 2 * 64 * CO;           // mu[64], scl[64], bet[64]
    float* redS = bnc + 192;
    float* redQ = redS + CO;

    const int t = threadIdx.x;
    const int tx = t % TC, ty = t / TC;
    const int r0 = blockIdx.x * MROWS;
    const int row = t / TPR;
    const int part = t % TPR;
    const int qc0 = part * CHUNK;

    if (t < CO) { redS[t] = 0.f; redQ[t] = 0.f; }
    if (APPLY_BN && t < 64) {
        float mu = sums[t] * invn;
        float var = fmaf(-mu, mu, sqs[t] * invn);
        bnc[t] = mu;
        bnc[64 + t] = gam[t] * rsqrtf(var + EPSV);
        bnc[128 + t] = bet[t];
    }
    __syncthreads();

    u64t acc[8][4];
    #pragma unroll
    for (int i = 0; i < 8; i++)
        #pragma unroll
        for (int c = 0; c < 4; c++) acc[i][c] = 0ULL;

    const int gr = r0 + row;

    // ---- gather helpers
    auto ldg_nbr = [&](int k) -> int {
        return (gr < Nr) ? __ldg(nbr + (size_t)k * Nr + gr) : Nr;
    };
    auto ldg_half = [&](int g, int qstart, float4* v) {
        const float4* src = (const float4*)(x + (size_t)g * 64) + qc0 + qstart;
        #pragma unroll
        for (int q = 0; q < HALF; q++) v[q] = src[q];
    };
    auto bn_sts = [&](float* XTw, const float4* vv, int qstart, int g) {
        #pragma unroll
        for (int q = 0; q < HALF; q++) {
            int qg = qc0 + qstart + q;
            float4 v = vv[q];
            if (APPLY_BN) {
                if (g >= Nr) { v.x = v.y = v.z = v.w = 0.f; }
                else {
                    float4 mu = ((const float4*)bnc)[qg];
                    float4 sc = ((const float4*)(bnc + 64))[qg];
                    float4 be = ((const float4*)(bnc + 128))[qg];
                    v.x = fmaxf(fmaf(v.x - mu.x, sc.x, be.x), 0.f);
                    v.y = fmaxf(fmaf(v.y - mu.y, sc.y, be.y), 0.f);
                    v.z = fmaxf(fmaf(v.z - mu.z, sc.z, be.z), 0.f);
                    v.w = fmaxf(fmaf(v.w - mu.w, sc.w, be.w), 0.f);
                }
            }
            float* dst = XTw + (4 * qg) * MROWS + row;
            dst[0 * MROWS] = v.x; dst[1 * MROWS] = v.y;
            dst[2 * MROWS] = v.z; dst[3 * MROWS] = v.w;
        }
    };
    auto w_ldg = [&](int k, float4* vW) {
        const float4* src = (const float4*)(W + (size_t)k * 64 * CO);
        #pragma unroll
        for (int i = 0; i < WCNT; i++) vW[i] = src[t + i * 256];
    };
    auto w_sts = [&](float* WSw, const float4* vW) {
        #pragma unroll
        for (int i = 0; i < WCNT; i++) ((float4*)WSw)[t + i * 256] = vW[i];
    };
    auto mma_half = [&](const float* XTr, const float* WSr, int j0) {
        #pragma unroll 8
        for (int jj = 0; jj < 32; jj++) {
            int j = j0 + jj;
            float4 a0 = ((const float4*)(XTr + j * MROWS))[ty];
            float4 a1 = ((const float4*)(XTr + j * MROWS + MROWS / 2))[ty];
            const u64t* wr = (const u64t*)(WSr + j * CO) + tx * 4;
            u64t b0 = wr[0], b1 = wr[1], b2 = wr[2], b3 = wr[3];
            u64t A[8] = { pack2(a0.x, a0.x), pack2(a0.y, a0.y), pack2(a0.z, a0.z), pack2(a0.w, a0.w),
                          pack2(a1.x, a1.x), pack2(a1.y, a1.y), pack2(a1.z, a1.z), pack2(a1.w, a1.w) };
            #pragma unroll
            for (int r = 0; r < 8; r++) {
                fma2(acc[r][0], A[r], b0);
                fma2(acc[r][1], A[r], b1);
                fma2(acc[r][2], A[r], b2);
                fma2(acc[r][3], A[r], b3);
            }
        }
    };

    // ---- prologue: stage 0
    {
        int g = ldg_nbr(0);
        float4 vA[HALF];
        ldg_half(g, 0, vA);    bn_sts(XT0, vA, 0, g);
        ldg_half(g, HALF, vA); bn_sts(XT0, vA, HALF, g);
        float4 vW[WCNT];
        w_ldg(0, vW); w_sts(WS0, vW);
    }
    __syncthreads();

    // ---- main loop: one sync per offset, gather k+1 under MMA of k
    for (int k = 0; k < 27; k++) {
        const float* XTr = (k & 1) ? XT1 : XT0;
        const float* WSr = (k & 1) ? WS1 : WS0;
        float* XTw = (k & 1) ? XT0 : XT1;
        float* WSw = (k & 1) ? WS0 : WS1;
        const bool pre = (k < 26);

        int g = Nr;
        float4 vA[HALF];
        if (pre) { g = ldg_nbr(k + 1); ldg_half(g, 0, vA); }

        mma_half(XTr, WSr, 0);

        float4 vB[HALF];
        float4 vW[WCNT];
        if (pre) {
            bn_sts(XTw, vA, 0, g);
            ldg_half(g, HALF, vB);
            w_ldg(k + 1, vW);
        }

        mma_half(XTr, WSr, 32);

        if (pre) {
            bn_sts(XTw, vB, HALF, g);
            w_sts(WSw, vW);
        }
        __syncthreads();
    }

    // ---- epilogue: store + fused BN stats partials
    float scol[8], qcol[8];
    #pragma unroll
    for (int c = 0; c < 8; c++) { scol[c] = 0.f; qcol[c] = 0.f; }
    #pragma unroll
    for (int i = 0; i < 8; i++) {
        int rr = (i < 4) ? (ty * 4 + i) : (MROWS / 2 + ty * 4 + (i - 4));
        int rowg = r0 + rr;
        float2 f0 = unpack2(acc[i][0]), f1 = unpack2(acc[i][1]);
        float2 f2 = unpack2(acc[i][2]), f3 = unpack2(acc[i][3]);
        if (rowg < Nr) {
            float4* o = (float4*)(out + (size_t)rowg * CO + tx * 8);
            o[0] = make_float4(f0.x, f0.y, f1.x, f1.y);
            o[1] = make_float4(f2.x, f2.y, f3.x, f3.y);
            float vs[8] = { f0.x, f0.y, f1.x, f1.y, f2.x, f2.y, f3.x, f3.y };
            #pragma unroll
            for (int c = 0; c < 8; c++) { scol[c] += vs[c]; qcol[c] = fmaf(vs[c], vs[c], qcol[c]); }
        }
    }
    #pragma unroll
    for (int c = 0; c < 8; c++) {
        atomicAdd(&redS[tx * 8 + c], scol[c]);
        atomicAdd(&redQ[tx * 8 + c], qcol[c]);
    }
    __syncthreads();
    if (t < CO) {
        atomicAdd(&oS[t], redS[t]);
        atomicAdd(&oQ[t], redQ[t]);
    }
}

// ---------------------------------------------------------------- BN apply (+pool) kernels
__global__ void __launch_bounds__(256) bn_apply_pool_kernel(const float* __restrict__ x,
                                                            const int* __restrict__ seg,
                                                            float* __restrict__ xp, int rows,
                                                            const float* __restrict__ gam, const float* __restrict__ bet,
                                                            const float* __restrict__ sums, const float* __restrict__ sqs) {
    size_t total = (size_t)rows * 64;
    float invn = 1.f / (float)rows;
    for (size_t idx = (size_t)blockIdx.x * 256 + threadIdx.x; idx < total; idx += (size_t)gridDim.x * 256) {
        int c = (int)(idx & 63);
        int r = (int)(idx >> 6);
        float mu = sums[c] * invn;
        float var = fmaf(-mu, mu, sqs[c] * invn);
        float scl = gam[c] * rsqrtf(var + EPSV);
        float v = fmaxf(fmaf(x[idx] - mu, scl, bet[c]), 0.f);
        atomicMax((unsigned int*)&xp[(size_t)seg[r] * 64 + c], __float_as_uint(v));
    }
}

template<int C>
__global__ void __launch_bounds__(256) bn_apply_kernel(const float* __restrict__ x, float* __restrict__ y,
                                                       int rows,
                                                       const float* __restrict__ gam, const float* __restrict__ bet,
                                                       const float* __restrict__ sums, const float* __restrict__ sqs) {
    size_t total = (size_t)rows * C;
    float invn = 1.f / (float)rows;
    for (size_t idx = (size_t)blockIdx.x * 256 + threadIdx.x; idx < total; idx += (size_t)gridDim.x * 256) {
        int c = (int)(idx & (C - 1));
        float mu = sums[c] * invn;
        float var = fmaf(-mu, mu, sqs[c] * invn);
        float scl = gam[c] * rsqrtf(var + EPSV);
        float v = fmaf(x[idx] - mu, scl, bet[c]);
        y[idx] = fmaxf(v, 0.f);
    }
}

// ---------------------------------------------------------------- launch
extern "C" void kernel_launch(void* const* d_in, const int* in_sizes, int n_in,
                              void* d_out, int out_size) {
    const float* feats = (const float*)d_in[0];
    const float* W1    = (const float*)d_in[1];
    const float* g1    = (const float*)d_in[3];
    const float* be1   = (const float*)d_in[4];
    const float* W2    = (const float*)d_in[5];
    const float* g2    = (const float*)d_in[7];
    const float* be2   = (const float*)d_in[8];
    const float* W3    = (const float*)d_in[9];
    const float* g3    = (const float*)d_in[11];
    const float* be3   = (const float*)d_in[12];
    const int* km_in   = (const int*)d_in[13];
    const int* km_out  = (const int*)d_in[14];
    const int* seg     = (const int*)d_in[15];
    const int* km2_in  = (const int*)d_in[16];
    const int* km2_out = (const int*)d_in[17];

    int N  = in_sizes[0];
    int M  = in_sizes[13] / 27;
    int M2 = in_sizes[16] / 27;
    int NP = out_size / 128;

    float *x1, *x2, *xp, *y3, *stats; int *nbr, *nbr2;
    cudaGetSymbolAddress((void**)&x1, g_x1);
    cudaGetSymbolAddress((void**)&x2, g_x2);
    cudaGetSymbolAddress((void**)&xp, g_xp);
    cudaGetSymbolAddress((void**)&y3, g_y3);
    cudaGetSymbolAddress((void**)&nbr, g_nbr);
    cudaGetSymbolAddress((void**)&nbr2, g_nbr2);
    cudaGetSymbolAddress((void**)&stats, g_stats);

    // dynamic smem sizes (floats): 2 X-stages + 2 W-stages + bn consts + reduce
    constexpr int SM2 = (2 * 64 * 256 + 2 * 64 * 64 + 192 + 2 * 64) * 4;    // 165 KB
    constexpr int SM3 = (2 * 64 * 128 + 2 * 64 * 128 + 192 + 2 * 128) * 4;  // 133 KB
    cudaFuncSetAttribute((const void*)conv_ffma_kernel<64, 256, true>,
                         cudaFuncAttributeMaxDynamicSharedMemorySize, SM2);
    cudaFuncSetAttribute((const void*)conv_ffma_kernel<128, 128, false>,
                         cudaFuncAttributeMaxDynamicSharedMemorySize, SM3);

    // (1) zero stats   (2) init tables/buffers   (3,4) build neighbor tables
    zstats_kernel<<<1, 768>>>(stats);
    initbig_kernel<<<(27 * N + 255) / 256, 256>>>(nbr, nbr2, xp, x1, N, NP);
    build_nbr_kernel<<<(27 * M + 255) / 256, 256>>>(km_in, km_out, nbr, M, N);
    build_nbr_kernel<<<(27 * M2 + 255) / 256, 256>>>(km2_in, km2_out, nbr2, M2, NP);

    // (5) layer 1 conv + fused stats
    conv1_kernel<<<(N + 63) / 64, 256>>>(feats, W1, x1, nbr, N, stats);

    // (6) layer 2 conv: inline BN1+ReLU on gather, fused stats2   <-- ncu capture target
    conv_ffma_kernel<64, 256, true><<<(N + 255) / 256, 256, SM2>>>(
        x1, W2, x2, nbr, N,
        stats + 0, stats + 128, g1, be1, 1.f / (float)N,
        stats + 256, stats + 384);

    // (7) BN2+ReLU fused with maxpool
    bn_apply_pool_kernel<<<1184, 256>>>(x2, seg, xp, N, g2, be2, stats + 256, stats + 384);

    // (8) layer 3 conv (no inline BN), fused stats3
    conv_ffma_kernel<128, 128, false><<<(NP + 127) / 128, 256, SM3>>>(
        xp, W3, y3, nbr2, NP,
        nullptr, nullptr, nullptr, nullptr, 0.f,
        stats + 512, stats + 640);

    // (9) BN3+ReLU -> output
    bn_apply_kernel<128><<<1184, 256>>>(y3, (float*)d_out, NP, g3, be3, stats + 512, stats + 640);
}